// round 13
// baseline (speedup 1.0000x reference)
#include <cuda_runtime.h>

#define NB     8
#define NATOM  512
#define NFEAT  42
#define NNEIGH 100
#define NPT    256
#define NH1    64
#define NH2    32

#define FT     384            // threads per block (divisible by 3!)
#define NEIB   256            // ei-role blocks (16 atoms each)
#define NPAIR  (NNEIGH*NFEAT) // 4200
#define NQ     (NPAIR*3/4)    // 3150 float4s per atom tile

// scratch for dE (input gradient) + per-batch completion flags
__device__ float g_dE[NB * NATOM * NFEAT];
__device__ int   g_done[NB];

__device__ __forceinline__ int ld_acquire(const int* p)
{
    int v;
    asm volatile("ld.acquire.gpu.b32 %0, [%1];" : "=r"(v) : "l"(p) : "memory");
    return v;
}
__device__ __forceinline__ void red_release_add(int* p, int v)
{
    asm volatile("red.release.gpu.global.add.s32 [%0], %1;" :: "l"(p), "r"(v) : "memory");
}

// fast tanh: clamped exp-based, well within 1e-3 rel-err budget
__device__ __forceinline__ float fast_tanh(float x)
{
    x = fminf(15.0f, fmaxf(-15.0f, x));
    const float e = __expf(2.0f * x);
    return __fdividef(e - 1.0f, e + 1.0f);
}

struct EiS {
    float sW0[NH1 * 43];
    float sW1[NH2 * 65];
    float sW2[NH2];
    float sb0[NH1];
    float sb1[NH2];
    float sb2v;
    float sx [16][NFEAT];
    float sh1[16][NH1];
    float sg2[16][NH2];
    float sg1[16][NH1];
};
struct FS {
    float sg[NPAIR];
    int   sn[NNEIGH];
    float red[FT / 32][3];
    float sred[8];
};
union SU { EiS e; FS f; };

__global__ void reset_kernel()
{
    if (threadIdx.x < NB) g_done[threadIdx.x] = 0;
}

// ---------------------------------------------------------------------------
// Fused kernel. Blocks [0,256): MLP fwd+bwd (2 atoms/warp, 16 atoms/block),
// then release g_done[batch]. Blocks [256, 256+4096): force for one atom,
// spin-wait (acquire) on the producing batch's flag before the dE gather.
// All ei blocks fit in scheduling wave 1 (256 < 148*occ), so no deadlock.
// ---------------------------------------------------------------------------
__global__ __launch_bounds__(FT, 5) void fused_kernel(
    const float* __restrict__ image,
    const float* __restrict__ dfeat,
    const int*   __restrict__ neighbor,
    const float* __restrict__ W0, const float* __restrict__ b0,
    const float* __restrict__ W1, const float* __restrict__ b1,
    const float* __restrict__ W2, const float* __restrict__ b2,
    float* __restrict__ out)
{
    __shared__ SU su;
    const int tid = threadIdx.x;

    if (blockIdx.x < NEIB) {
        // ================= ei role: 16 atoms, 2 per warp =================
        EiS& S = su.e;
        const int w = tid >> 5;          // warp id; warps 0..7 compute
        const int l = tid & 31;

        const int base = blockIdx.x * 16;    // never crosses type boundary
        const int b    = base / NATOM;
        const int a0   = base % NATOM;
        const int t    = a0 / NPT;

        for (int i = tid; i < NH1 * NFEAT; i += FT) {
            int r = i / NFEAT, c = i - r * NFEAT;
            S.sW0[r * 43 + c] = W0[t * NH1 * NFEAT + i];
        }
        for (int i = tid; i < NH2 * NH1; i += FT) {
            int r = i >> 6, c = i & 63;
            S.sW1[r * 65 + c] = W1[t * NH2 * NH1 + i];
        }
        if (tid < NH2) S.sW2[tid] = W2[t * NH2 + tid];
        if (tid < NH1) S.sb0[tid] = b0[t * NH1 + tid];
        if (tid < NH2) S.sb1[tid] = b1[t * NH2 + tid];
        if (tid == 0)  S.sb2v = b2[t];
        __syncthreads();

        if (w < 8) {
            const int gA = b * NATOM + (a0 + w);
            const int gB = gA + 8;
            const int wB = w + 8;

            if (l < NFEAT) {
                S.sx[w][l]  = image[gA * NFEAT + l];
                S.sx[wB][l] = image[gB * NFEAT + l];
            }
            if (l < NFEAT - 32) {
                S.sx[w][32 + l]  = image[gA * NFEAT + 32 + l];
                S.sx[wB][32 + l] = image[gB * NFEAT + 32 + l];
            }
            __syncwarp();

            float s1a = S.sb0[l], s2a = S.sb0[32 + l];
            float s1b = s1a,      s2b = s2a;
            #pragma unroll
            for (int f = 0; f < NFEAT; f++) {
                const float w0a = S.sW0[l * 43 + f];
                const float w0b = S.sW0[(32 + l) * 43 + f];
                const float xa  = S.sx[w][f];
                const float xb  = S.sx[wB][f];
                s1a += xa * w0a;  s2a += xa * w0b;
                s1b += xb * w0a;  s2b += xb * w0b;
            }
            const float h1aA = fast_tanh(s1a), h1bA = fast_tanh(s2a);
            const float h1aB = fast_tanh(s1b), h1bB = fast_tanh(s2b);
            S.sh1[w][l]  = h1aA; S.sh1[w][32 + l]  = h1bA;
            S.sh1[wB][l] = h1aB; S.sh1[wB][32 + l] = h1bB;
            __syncwarp();

            float sA = S.sb1[l], sB = S.sb1[l];
            #pragma unroll
            for (int i = 0; i < NH1; i++) {
                const float w1 = S.sW1[l * 65 + i];
                sA += S.sh1[w][i]  * w1;
                sB += S.sh1[wB][i] * w1;
            }
            const float h2A = fast_tanh(sA), h2B = fast_tanh(sB);
            const float w2v = S.sW2[l];
            S.sg2[w][l]  = w2v * (1.0f - h2A * h2A);
            S.sg2[wB][l] = w2v * (1.0f - h2B * h2B);

            float vA = h2A * w2v, vB = h2B * w2v;
            #pragma unroll
            for (int o = 16; o > 0; o >>= 1) {
                vA += __shfl_down_sync(0xffffffffu, vA, o);
                vB += __shfl_down_sync(0xffffffffu, vB, o);
            }
            if (l == 0) { out[8 + gA] = vA + S.sb2v; out[8 + gB] = vB + S.sb2v; }
            __syncwarp();

            float t1a = 0.0f, t2a = 0.0f, t1b = 0.0f, t2b = 0.0f;
            #pragma unroll
            for (int j = 0; j < NH2; j++) {
                const float w1a = S.sW1[j * 65 + l];
                const float w1b = S.sW1[j * 65 + 32 + l];
                const float ga  = S.sg2[w][j];
                const float gb  = S.sg2[wB][j];
                t1a += ga * w1a;  t2a += ga * w1b;
                t1b += gb * w1a;  t2b += gb * w1b;
            }
            S.sg1[w][l]       = t1a * (1.0f - h1aA * h1aA);
            S.sg1[w][32 + l]  = t2a * (1.0f - h1bA * h1bA);
            S.sg1[wB][l]      = t1b * (1.0f - h1aB * h1aB);
            S.sg1[wB][32 + l] = t2b * (1.0f - h1bB * h1bB);
            __syncwarp();

            const int c2 = (l < NFEAT - 32) ? (32 + l) : 0;
            float d1a = 0.0f, d2a = 0.0f, d1b = 0.0f, d2b = 0.0f;
            #pragma unroll
            for (int i = 0; i < NH1; i++) {
                const float w0a = S.sW0[i * 43 + l];
                const float w0b = S.sW0[i * 43 + c2];
                const float ga  = S.sg1[w][i];
                const float gb  = S.sg1[wB][i];
                d1a += ga * w0a;  d2a += ga * w0b;
                d1b += gb * w0a;  d2b += gb * w0b;
            }
            if (l < NFEAT) {
                g_dE[gA * NFEAT + l] = d1a;
                g_dE[gB * NFEAT + l] = d1b;
            }
            if (l < NFEAT - 32) {
                g_dE[gA * NFEAT + 32 + l] = d2a;
                g_dE[gB * NFEAT + 32 + l] = d2b;
            }
        }

        // publish: everyone fences own stores, then one release-add
        __threadfence();
        __syncthreads();
        if (tid == 0) red_release_add(&g_done[blockIdx.x / 32], 1);
        return;
    }

    // ================= force role: one atom per block =================
    FS& S = su.f;
    const int gidx = blockIdx.x - NEIB;      // b*NATOM + a
    const int b    = gidx >> 9;              // / NATOM

    if (tid < NNEIGH)
        S.sn[tid] = neighbor[gidx * NNEIGH + tid];

    // wait for producing batch (and, for Etot blocks, batch gidx's Ei)
    if (tid == 0) {
        while (ld_acquire(&g_done[b]) < 32) { }
        if (gidx < NB)
            while (ld_acquire(&g_done[gidx]) < 32) { }
    }
    __syncthreads();

    // fused Etot partial (blocks 0..7, first 256 threads): deterministic
    if (gidx < NB && tid < 256) {
        const float* Ei = out + 8 + gidx * NATOM;
        float v = Ei[tid] + Ei[tid + 256];
        #pragma unroll
        for (int o = 16; o > 0; o >>= 1) v += __shfl_down_sync(0xffffffffu, v, o);
        if ((tid & 31) == 0) S.sred[tid >> 5] = v;
    }

    // Gather: one L2 load per (n,f) pair; index 0 -> zero pad row
    for (int p = tid; p < NPAIR; p += FT) {
        const int n = p / NFEAT;
        const int f = p - n * NFEAT;
        const int j = S.sn[n];
        S.sg[p] = j ? g_dE[(b * NATOM + (j - 1)) * NFEAT + f] : 0.0f;
    }
    __syncthreads();

    if (gidx < NB && tid == 0) {
        float s = 0.0f;
        #pragma unroll
        for (int ww = 0; ww < 8; ww++) s += S.sred[ww];
        out[gidx] = s;
    }

    const float4* __restrict__ df = (const float4*)(dfeat + (long)gidx * (NPAIR * 3));

    const int  phase = tid % 3;              // == q mod 3 for all iterations
    const int  m0    = (4 * tid) / 3;
    const bool s1hi  = (phase == 2);         // slot1 uses gB iff phase==2
    const bool s2hi  = (phase >= 1);         // slot2 uses gB iff phase>=1

    float a0 = 0.0f, a1 = 0.0f, a2 = 0.0f, a3 = 0.0f;

    // 8 unconditional iterations: q = tid + it*384 <= 3071 < 3150
    #pragma unroll
    for (int it = 0; it < 8; it++) {
        const int q = tid + it * FT;
        const int m = m0 + it * 512;
        const float4 v = df[q];
        const float gA = S.sg[m];
        const float gB = S.sg[m + 1];
        a0 += gA * v.x;
        a1 += (s1hi ? gB : gA) * v.y;
        a2 += (s2hi ? gB : gA) * v.z;
        a3 += gB * v.w;
    }
    // tail: it = 8, valid iff tid < 3150 - 3072 = 78
    if (tid < NQ - 8 * FT) {
        const int q = tid + 8 * FT;
        const int m = m0 + 8 * 512;           // m0 max 102 -> 4198+1 < 4200
        const float4 v = df[q];
        const float gA = S.sg[m];
        const float gB = S.sg[m + 1];
        a0 += gA * v.x;
        a1 += (s1hi ? gB : gA) * v.y;
        a2 += (s2hi ? gB : gA) * v.z;
        a3 += gB * v.w;
    }

    // map slot accumulators to (x,y,z):  k(s) = (phase + s) mod 3
    float ax, ay, az;
    if (phase == 0)      { ax = a0 + a3; ay = a1;      az = a2;      }
    else if (phase == 1) { ax = a2;      ay = a0 + a3; az = a1;      }
    else                 { ax = a1;      ay = a2;      az = a0 + a3; }

    #pragma unroll
    for (int o = 16; o > 0; o >>= 1) {
        ax += __shfl_down_sync(0xffffffffu, ax, o);
        ay += __shfl_down_sync(0xffffffffu, ay, o);
        az += __shfl_down_sync(0xffffffffu, az, o);
    }
    const int w = tid >> 5, l = tid & 31;
    if (l == 0) { S.red[w][0] = ax; S.red[w][1] = ay; S.red[w][2] = az; }
    __syncthreads();
    if (tid < 3) {
        float s = 0.0f;
        #pragma unroll
        for (int ww = 0; ww < FT / 32; ww++) s += S.red[ww][tid];
        out[8 + NB * NATOM + gidx * 3 + tid] = s;
    }
}

// ---------------------------------------------------------------------------
// Launch: out layout = [Etot(8) | Ei(4096) | Force(12288)] = 16392 f32
// ---------------------------------------------------------------------------
extern "C" void kernel_launch(void* const* d_in, const int* in_sizes, int n_in,
                              void* d_out, int out_size)
{
    const float* image    = (const float*)d_in[0];
    const float* dfeat    = (const float*)d_in[1];
    const int*   neighbor = (const int*)d_in[2];
    // d_in[3] = natoms_img (unused)
    const float* W0 = (const float*)d_in[4];
    const float* b0 = (const float*)d_in[5];
    const float* W1 = (const float*)d_in[6];
    const float* b1 = (const float*)d_in[7];
    const float* W2 = (const float*)d_in[8];
    const float* b2 = (const float*)d_in[9];
    float* out = (float*)d_out;

    reset_kernel<<<1, 32>>>();
    fused_kernel<<<NEIB + NB * NATOM, FT>>>(image, dfeat, neighbor,
                                            W0, b0, W1, b1, W2, b2, out);
}